// round 7
// baseline (speedup 1.0000x reference)
#include <cuda_runtime.h>
#include <cuda_bf16.h>

#define BB   8
#define NN   32768
#define KK   20
#define CHN  16
#define NPTS (BB * 32768)

__device__ int g_idx_shift;  // 1 -> idx is int64, 0 -> int32

// Parallel width detect: odd 32-bit words all zero <=> little-endian int64.
__global__ void detect_idx_kernel(const unsigned int* __restrict__ idx32) {
    unsigned int any = idx32[2 * threadIdx.x + 1] | idx32[2 * threadIdx.x + 257];
    any = __ballot_sync(0xffffffffu, any != 0);
    __shared__ unsigned int warp_any[4];
    if ((threadIdx.x & 31) == 0) warp_any[threadIdx.x >> 5] = any;
    __syncthreads();
    if (threadIdx.x == 0)
        g_idx_shift = ((warp_any[0] | warp_any[1] | warp_any[2] | warp_any[3]) == 0) ? 1 : 0;
}

#define L2E 1.44269504088896f   // log2(e)
#define ZSH 20.0f               // fixed softmax shift (range guard, shift-invariant)

// ONE WARP PER POINT. lane = (kk, q): kk = lane>>2 is the k-offset within an
// 8-wide k chunk, q = lane&3 is the channel quarter [4q, 4q+4).
// Edge_o stores are warp-contiguous 512B (lane*16B) -> minimal L1 wavefronts.
__global__ void __launch_bounds__(128, 10)
gap_kernel(const float* __restrict__ x,
           const int*   __restrict__ idx32,
           const float* __restrict__ w1,  const float* __restrict__ g1,
           const float* __restrict__ b1,  const float* __restrict__ m1,
           const float* __restrict__ v1,
           const float* __restrict__ w2,  const float* __restrict__ g2,
           const float* __restrict__ b2,  const float* __restrict__ m2,
           const float* __restrict__ v2,
           const float* __restrict__ w1n, const float* __restrict__ g1n,
           const float* __restrict__ b1n, const float* __restrict__ m1n,
           const float* __restrict__ v1n,
           const float* __restrict__ w2n, const float* __restrict__ g2n,
           const float* __restrict__ b2n, const float* __restrict__ m2n,
           const float* __restrict__ v2n,
           float* __restrict__ out, float* __restrict__ edge_o)
{
    // ---- fold BN into affine constants ----
    __shared__ float sA1[CHN], sB1[CHN], sC1[CHN], sW2[CHN];
    __shared__ float sAn[CHN], sBn[CHN], sCn[CHN], sWn[CHN];
    __shared__ float sZC;

    int t = threadIdx.x;
    if (t < CHN) {
        float s1 = g1[t] * rsqrtf(v1[t] + 1e-5f);
        sA1[t] = w1[2*t]     * s1;
        sB1[t] = w1[2*t + 1] * s1;
        sC1[t] = b1[t] - m1[t] * s1;
        float s2 = g2[0] * rsqrtf(v2[0] + 1e-5f);
        sW2[t] = w2[t] * s2;

        float s1n = g1n[t] * rsqrtf(v1n[t] + 1e-5f);
        sAn[t] = w1n[2*t]     * s1n;
        sBn[t] = w1n[2*t + 1] * s1n;
        sCn[t] = b1n[t] - m1n[t] * s1n;
        float s2n = g2n[0] * rsqrtf(v2n[0] + 1e-5f);
        sWn[t] = w2n[t] * s2n;

        if (t == 0) {
            float c2  = b2[0]  - m2[0]  * (g2[0]  * rsqrtf(v2[0]  + 1e-5f));
            float c2n = b2n[0] - m2n[0] * (g2n[0] * rsqrtf(v2n[0] + 1e-5f));
            sZC = c2 + c2n;
        }
    }
    __syncthreads();

    int w  = (blockIdx.x * 128 + t) >> 5;   // global warp id == point id
    int l  = t & 31;                        // lane
    int kk = l >> 2;                        // k offset within chunk (0..7)
    int q  = l & 3;                         // channel quarter
    int c0 = q << 2;
    int p  = w;
    int b  = p >> 15;                       // N = 2^15
    int n  = p & 32767;

    const float* xrow = x + b * NN;
    float xc = __ldg(xrow + n);             // same addr warp-wide -> broadcast

    // per-thread folded constants for this quarter's 4 channels
    float A1h[4], D1h[4], Anh[4], Dnh[4], W2h[4], Wnh[4];
#pragma unroll
    for (int c = 0; c < 4; c++) {
        int cc = c0 + c;
        A1h[c] = sA1[cc];
        D1h[c] = fmaf(sB1[cc], xc, sC1[cc]);
        Anh[c] = sAn[cc];
        Dnh[c] = fmaf(sBn[cc], xc, sCn[cc]);
        W2h[c] = sW2[cc];
        Wnh[c] = sWn[cc];
    }
    float zc = sZC;

    // ---- load this point's 20 indices: lane l (<20) holds idx[k=l] ----
    int myidx = 0;
    if (l < KK) {
        if (g_idx_shift) myidx = __ldg(idx32 + (size_t)p * (2 * KK) + 2 * l);
        else             myidx = __ldg(idx32 + (size_t)p * KK + l);
    }

    float acc[4];
#pragma unroll
    for (int c = 0; c < 4; c++) acc[c] = 0.0f;
    float ssum = 0.0f;

    float* ep = edge_o + (size_t)p * (KK * CHN);

    // ---- 3 chunks: k = [0,8), [8,16), [16,20) ----
#pragma unroll
    for (int ch = 0; ch < 3; ch++) {
        int kg     = ch * 8 + kk;           // this lane's global k
        bool live  = (kg < KK);

        // fetch my k's neighbor value (4 q-lanes share the address -> broadcast)
        int   xik = __shfl_sync(0xffffffffu, myidx, kg & 31);
        float xvk = __ldg(xrow + (live ? xik : 0));
        float d   = xvk - xc;

        float eo[4];
        float s = 0.0f;
#pragma unroll
        for (int c = 0; c < 4; c++) {
            float t1 = fmaf(A1h[c], d, D1h[c]);
            t1 = fmaxf(t1, 0.2f * t1);          // lrelu
            s  = fmaf(W2h[c], t1, s);
            float tn = fmaf(Anh[c], d, Dnh[c]);
            tn = fmaxf(tn, 0.2f * tn);
            eo[c] = tn;
            s  = fmaf(Wnh[c], tn, s);
        }
        // combine the four quarters' partial logits (within q-group of 4)
        s += __shfl_xor_sync(0xffffffffu, s, 1);
        s += __shfl_xor_sync(0xffffffffu, s, 2);
        float z = zc + s;
        z = fmaxf(z, 0.2f * z);                 // lrelu(a+e)

        // fixed-shift softmax numerator
        float pk = exp2f(fmaf(z, L2E, -(ZSH * L2E)));
        pk = live ? pk : 0.0f;

        ssum += pk;
#pragma unroll
        for (int c = 0; c < 4; c++)
            acc[c] = fmaf(pk, eo[c], acc[c]);

        // warp-contiguous 512B store: byte addr = p*1280 + ch*512 + lane*16
        if (live)
            __stcs((float4*)(ep + kg * CHN + c0), make_float4(eo[0], eo[1], eo[2], eo[3]));
    }

    // ---- reduce acc/ssum across the 8 kk-lanes (same q) ----
#pragma unroll
    for (int off = 4; off < 32; off <<= 1) {
        ssum += __shfl_xor_sync(0xffffffffu, ssum, off);
#pragma unroll
        for (int c = 0; c < 4; c++)
            acc[c] += __shfl_xor_sync(0xffffffffu, acc[c], off);
    }

    if (kk == 0) {                          // lanes 0..3 write 64B contiguous
        float inv = 1.0f / ssum;
        float* op = out + (size_t)p * CHN + c0;
        __stcs((float4*)op, make_float4(acc[0]*inv, acc[1]*inv, acc[2]*inv, acc[3]*inv));
    }
}

extern "C" void kernel_launch(void* const* d_in, const int* in_sizes, int n_in,
                              void* d_out, int out_size) {
    const float* x    = (const float*)d_in[0];
    // d_in[1] = pos (unused), d_in[3] = dis (unused)
    const int*   idx  = (const int*)d_in[2];
    const float* w1   = (const float*)d_in[4];
    const float* g1   = (const float*)d_in[5];
    const float* b1   = (const float*)d_in[6];
    const float* m1   = (const float*)d_in[7];
    const float* v1   = (const float*)d_in[8];
    const float* w2   = (const float*)d_in[9];
    const float* g2   = (const float*)d_in[10];
    const float* b2   = (const float*)d_in[11];
    const float* m2   = (const float*)d_in[12];
    const float* v2   = (const float*)d_in[13];
    const float* w1n  = (const float*)d_in[14];
    const float* g1n  = (const float*)d_in[15];
    const float* b1n  = (const float*)d_in[16];
    const float* m1n  = (const float*)d_in[17];
    const float* v1n  = (const float*)d_in[18];
    const float* w2n  = (const float*)d_in[19];
    const float* g2n  = (const float*)d_in[20];
    const float* b2n  = (const float*)d_in[21];
    const float* m2n  = (const float*)d_in[22];
    const float* v2n  = (const float*)d_in[23];

    float* out  = (float*)d_out;                         // (B,N,CH) first
    float* edge = out + (size_t)NPTS * CHN;              // then (B,N,K,CH)

    detect_idx_kernel<<<1, 128>>>((const unsigned int*)idx);
    // one warp per point: NPTS warps, 4 warps per 128-thread block
    gap_kernel<<<NPTS / 4, 128>>>(x, idx,
                                    w1, g1, b1, m1, v1, w2, g2, b2, m2, v2,
                                    w1n, g1n, b1n, m1n, v1n, w2n, g2n, b2n, m2n, v2n,
                                    out, edge);
}

// round 9
// speedup vs baseline: 1.8960x; 1.8960x over previous
#include <cuda_runtime.h>
#include <cuda_bf16.h>

#define BB   8
#define NN   32768
#define KK   20
#define CHN  16
#define NPTS (BB * 32768)

__device__ int g_idx_shift;  // 1 -> idx is int64, 0 -> int32

// Parallel width detect: odd 32-bit words all zero <=> little-endian int64.
__global__ void detect_idx_kernel(const unsigned int* __restrict__ idx32) {
    unsigned int any = idx32[2 * threadIdx.x + 1] | idx32[2 * threadIdx.x + 257];
    any = __ballot_sync(0xffffffffu, any != 0);
    __shared__ unsigned int warp_any[4];
    if ((threadIdx.x & 31) == 0) warp_any[threadIdx.x >> 5] = any;
    __syncthreads();
    if (threadIdx.x == 0)
        g_idx_shift = ((warp_any[0] | warp_any[1] | warp_any[2] | warp_any[3]) == 0) ? 1 : 0;
}

#define L2E 1.44269504088896f   // log2(e)
#define ZSH 20.0f               // fixed softmax shift (range guard, shift-invariant)

// 8 lanes per point. Per iteration kp the group handles k = 2kp (lanes 0-3,
// quarters 0-3) and k = 2kp+1 (lanes 4-7, quarters 0-3). Each lane's eo[4] is
// exactly the 16B chunk it stores -> warp STG.128 covers 4 FULL 128B lines.
__global__ void __launch_bounds__(128, 10)
gap_kernel(const float* __restrict__ x,
           const int*   __restrict__ idx32,
           const float* __restrict__ w1,  const float* __restrict__ g1,
           const float* __restrict__ b1,  const float* __restrict__ m1,
           const float* __restrict__ v1,
           const float* __restrict__ w2,  const float* __restrict__ g2,
           const float* __restrict__ b2,  const float* __restrict__ m2,
           const float* __restrict__ v2,
           const float* __restrict__ w1n, const float* __restrict__ g1n,
           const float* __restrict__ b1n, const float* __restrict__ m1n,
           const float* __restrict__ v1n,
           const float* __restrict__ w2n, const float* __restrict__ g2n,
           const float* __restrict__ b2n, const float* __restrict__ m2n,
           const float* __restrict__ v2n,
           float* __restrict__ out, float* __restrict__ edge_o)
{
    // ---- fold BN into affine constants ----
    __shared__ float sA1[CHN], sB1[CHN], sC1[CHN], sW2[CHN];
    __shared__ float sAn[CHN], sBn[CHN], sCn[CHN], sWn[CHN];
    __shared__ float sZC;

    int t = threadIdx.x;
    if (t < CHN) {
        float s1 = g1[t] * rsqrtf(v1[t] + 1e-5f);
        sA1[t] = w1[2*t]     * s1;
        sB1[t] = w1[2*t + 1] * s1;
        sC1[t] = b1[t] - m1[t] * s1;
        float s2 = g2[0] * rsqrtf(v2[0] + 1e-5f);
        sW2[t] = w2[t] * s2;

        float s1n = g1n[t] * rsqrtf(v1n[t] + 1e-5f);
        sAn[t] = w1n[2*t]     * s1n;
        sBn[t] = w1n[2*t + 1] * s1n;
        sCn[t] = b1n[t] - m1n[t] * s1n;
        float s2n = g2n[0] * rsqrtf(v2n[0] + 1e-5f);
        sWn[t] = w2n[t] * s2n;

        if (t == 0) {
            float c2  = b2[0]  - m2[0]  * (g2[0]  * rsqrtf(v2[0]  + 1e-5f));
            float c2n = b2n[0] - m2n[0] * (g2n[0] * rsqrtf(v2n[0] + 1e-5f));
            sZC = c2 + c2n;
        }
    }
    __syncthreads();

    int g   = blockIdx.x * 128 + t;
    int p   = g >> 3;                   // point id (8 lanes per point)
    int l   = t & 31;                   // lane in warp
    int l8  = l & 7;                    // lane within 8-lane point group
    int q   = l & 3;                    // channel quarter
    int hi  = (l >> 2) & 1;             // k parity handled by this lane
    int c0  = q << 2;
    int b   = p >> 15;                  // N = 2^15
    int n   = p & 32767;
    int gb  = l & 24;                   // group base lane (for shfl source)

    const float* xrow = x + b * NN;
    float xc = __ldg(xrow + n);         // 4 consecutive addrs per warp -> 1 line

    // per-thread folded constants for this quarter's 4 channels
    float A1h[4], D1h[4], Anh[4], Dnh[4], W2h[4], Wnh[4];
#pragma unroll
    for (int c = 0; c < 4; c++) {
        int cc = c0 + c;
        A1h[c] = sA1[cc];
        D1h[c] = fmaf(sB1[cc], xc, sC1[cc]);
        Anh[c] = sAn[cc];
        Dnh[c] = fmaf(sBn[cc], xc, sCn[cc]);
        W2h[c] = sW2[cc];
        Wnh[c] = sWn[cc];
    }
    float zc = sZC;

    // ---- cooperative gather: lane l8 loads k = l8, l8+8, (l8+16 if l8<4) ----
    float xr[3];
    {
        int i0, i1, i2 = 0;
        if (g_idx_shift) {              // int64: word index 2*(20p + k)
            const int* ipb = idx32 + (size_t)p * (2 * KK) + 2 * l8;
            i0 = __ldg(ipb + 0);
            i1 = __ldg(ipb + 16);
            if (l8 < 4) i2 = __ldg(ipb + 32);
        } else {                        // int32
            const int* ipb = idx32 + (size_t)p * KK + l8;
            i0 = __ldg(ipb + 0);
            i1 = __ldg(ipb + 8);
            if (l8 < 4) i2 = __ldg(ipb + 16);
        }
        xr[0] = __ldg(xrow + i0);
        xr[1] = __ldg(xrow + i1);
        xr[2] = __ldg(xrow + (l8 < 4 ? i2 : 0));
    }

    float acc[4];
#pragma unroll
    for (int c = 0; c < 4; c++) acc[c] = 0.0f;
    float ssum = 0.0f;

    float* ep = edge_o + (size_t)p * (KK * CHN);   // this point's 1280B block

#pragma unroll
    for (int kp = 0; kp < KK / 2; kp++) {
        int klane = 2 * kp + hi;        // this lane's k
        // broadcast xv[klane] from the group lane that gathered it
        float xvk = __shfl_sync(0xffffffffu, xr[kp >> 2], gb | (klane & 7));
        float d = xvk - xc;

        float eo[4];
        float s = 0.0f;
#pragma unroll
        for (int c = 0; c < 4; c++) {
            float t1 = fmaf(A1h[c], d, D1h[c]);
            t1 = fmaxf(t1, 0.2f * t1);          // lrelu
            s  = fmaf(W2h[c], t1, s);
            float tn = fmaf(Anh[c], d, Dnh[c]);
            tn = fmaxf(tn, 0.2f * tn);
            eo[c] = tn;
            s  = fmaf(Wnh[c], tn, s);
        }
        // reduce the 4 quarters' partial logits (within the 4-lane k-subgroup)
        s += __shfl_xor_sync(0xffffffffu, s, 1);
        s += __shfl_xor_sync(0xffffffffu, s, 2);
        float z = zc + s;
        z = fmaxf(z, 0.2f * z);                 // lrelu(a+e)

        // fixed-shift softmax numerator
        float pk = exp2f(fmaf(z, L2E, -(ZSH * L2E)));
        ssum += pk;
#pragma unroll
        for (int c = 0; c < 4; c++)
            acc[c] = fmaf(pk, eo[c], acc[c]);

        // coalesced store: warp covers 4 points x 128B FULL lines
        __stcs((float4*)(ep + kp * 32 + l8 * 4), make_float4(eo[0], eo[1], eo[2], eo[3]));
    }

    // ---- combine the two k-parity halves (lane l <-> l^4) ----
    ssum += __shfl_xor_sync(0xffffffffu, ssum, 4);
#pragma unroll
    for (int c = 0; c < 4; c++)
        acc[c] += __shfl_xor_sync(0xffffffffu, acc[c], 4);

    if (hi == 0) {                      // lanes 0-3 of each group write 64B
        float inv = 1.0f / ssum;
        float* op = out + (size_t)p * CHN + c0;
        __stcs((float4*)op, make_float4(acc[0]*inv, acc[1]*inv, acc[2]*inv, acc[3]*inv));
    }
}

extern "C" void kernel_launch(void* const* d_in, const int* in_sizes, int n_in,
                              void* d_out, int out_size) {
    const float* x    = (const float*)d_in[0];
    // d_in[1] = pos (unused), d_in[3] = dis (unused)
    const int*   idx  = (const int*)d_in[2];
    const float* w1   = (const float*)d_in[4];
    const float* g1   = (const float*)d_in[5];
    const float* b1   = (const float*)d_in[6];
    const float* m1   = (const float*)d_in[7];
    const float* v1   = (const float*)d_in[8];
    const float* w2   = (const float*)d_in[9];
    const float* g2   = (const float*)d_in[10];
    const float* b2   = (const float*)d_in[11];
    const float* m2   = (const float*)d_in[12];
    const float* v2   = (const float*)d_in[13];
    const float* w1n  = (const float*)d_in[14];
    const float* g1n  = (const float*)d_in[15];
    const float* b1n  = (const float*)d_in[16];
    const float* m1n  = (const float*)d_in[17];
    const float* v1n  = (const float*)d_in[18];
    const float* w2n  = (const float*)d_in[19];
    const float* g2n  = (const float*)d_in[20];
    const float* b2n  = (const float*)d_in[21];
    const float* m2n  = (const float*)d_in[22];
    const float* v2n  = (const float*)d_in[23];

    float* out  = (float*)d_out;                         // (B,N,CH) first
    float* edge = out + (size_t)NPTS * CHN;              // then (B,N,K,CH)

    detect_idx_kernel<<<1, 128>>>((const unsigned int*)idx);
    // 8 lanes per point: NPTS*8 threads
    gap_kernel<<<(NPTS * 8) / 128, 128>>>(x, idx,
                                    w1, g1, b1, m1, v1, w2, g2, b2, m2, v2,
                                    w1n, g1n, b1n, m1n, v1n, w2n, g2n, b2n, m2n, v2n,
                                    out, edge);
}